// round 16
// baseline (speedup 1.0000x reference)
#include <cuda_runtime.h>
#include <cstdint>

// BinaryTree hierarchical-softmax forward:
//   z = W[leaf(input)], path = 21 root-to-leaf nodes of context vertex
//   out[b] = prod_i sigmoid(dot(W[path_i], z)) = 1 / prod_i (1 + exp(-s_i))
//
// d_in[0]: collocation int32 [65536, 2]
// d_in[1]: W float32 [2097151, 128]
// d_out  : float32 [65536]
//
// Dual-source streams. Bytes-in-flight is capped by landing space, and the
// R4 register pipeline already commits 176KB of the 256KB regfile. Fix: add
// smem as a second landing buffer. Even elements use R4's exact 22-row
// register burst; odd elements land in a warp-private 22-row smem stage via
// cp.async.ca (zero registers; .ca keeps L1-resident shallow rows out of
// L2). Each loop processes one even + one odd element, and each stream's
// burst is issued one full loop (~2 element-times) ahead -> exposed DRAM
// latency collapses. Single stage per warp: all LDS reads complete (issued
// first, ~10cyc to smem access) long before the refill LDGSTS writes land
// (>=200cyc after issue). One commit_group per loop; wait_group 0 at the
// odd phase. NO register cap (R5: caps spill the burst).

#define DEPTH   20
#define NPATH   21
#define OFFSET  1048575u             // (1<<DEPTH)-1
#define NDIM    128
#define BATCH   65536

__device__ __forceinline__ void cp16(uint32_t dst, const void* src) {
    asm volatile("cp.async.ca.shared.global [%0], [%1], 16;" :: "r"(dst), "l"(src));
}

__global__ __launch_bounds__(64)
void BinaryTree_65927747993695_kernel(const int* __restrict__ coll,
                                      const float* __restrict__ W,
                                      float* __restrict__ out)
{
    // [warp-in-block][row: 0=z, 1..21=path levels 0..20][lane] : 11.3KB/warp
    __shared__ float4 ring[2][NPATH + 1][32];

    const int tid    = blockIdx.x * blockDim.x + threadIdx.x;
    const int gw     = tid >> 5;
    const int lane   = tid & 31;
    const int wib    = (threadIdx.x >> 5) & 1;
    const int stride = (gridDim.x * blockDim.x) >> 5;
    const int s2     = 2 * stride;

    int e0 = gw;
    if (e0 >= BATCH) return;

    const float4* __restrict__ Wl  = (const float4*)W + lane;
    const float4* __restrict__ Wm1 = Wl - (NDIM / 4);   // path "-1" folded in
    const int2*   __restrict__ c2  = (const int2*)coll;

    // --- prologue: coll for e0 .. e0+3s ---
    int  e1 = e0 + stride, e2 = e0 + s2, e3 = e2 + stride;
    int2 cv0 = __ldg(c2 + e0);
    int2 cv1 = (e1 < BATCH) ? __ldg(c2 + e1) : make_int2(0, 0);
    int2 cv2 = (e2 < BATCH) ? __ldg(c2 + e2) : make_int2(0, 0);
    int2 cv3 = (e3 < BATCH) ? __ldg(c2 + e3) : make_int2(0, 0);

    // even stream: register burst for e0 (R4 shape)
    float4 z, w[NPATH];
    {
        z = __ldg(Wl + (size_t)((unsigned)cv0.x + OFFSET) * (NDIM / 4));
        const unsigned b = (unsigned)cv0.y + OFFSET + 1u;
#pragma unroll
        for (int i = 0; i < NPATH; ++i)
            w[i] = __ldg(Wm1 + (size_t)(b >> (DEPTH - i)) * (NDIM / 4));
    }

    // odd stream: cp.async stage for e1
    if (e1 < BATCH) {
        uint32_t d0 = (uint32_t)__cvta_generic_to_shared(&ring[wib][0][lane]);
        cp16(d0, Wl + (size_t)((unsigned)cv1.x + OFFSET) * (NDIM / 4));
        const unsigned bb = (unsigned)cv1.y + OFFSET + 1u;
#pragma unroll
        for (int i = 0; i < NPATH; ++i) {
            uint32_t d = (uint32_t)__cvta_generic_to_shared(&ring[wib][1 + i][lane]);
            cp16(d, Wm1 + (size_t)(bb >> (DEPTH - i)) * (NDIM / 4));
        }
    }
    asm volatile("cp.async.commit_group;" ::: "memory");

    for (;;) {
        // coll for the NEXT loop's streams (e0+4s, e0+5s)
        const int e4 = e2 + s2, e5 = e3 + s2;
        const int2 cv4 = (e4 < BATCH) ? __ldg(c2 + e4) : make_int2(0, 0);
        const int2 cv5 = (e5 < BATCH) ? __ldg(c2 + e5) : make_int2(0, 0);

        float a[32];

        // ===== EVEN phase: element e0 from registers (R4 body) =====
#pragma unroll
        for (int i = 0; i < NPATH; ++i)
            a[i] = w[i].x * z.x + w[i].y * z.y + w[i].z * z.z + w[i].w * z.w;
#pragma unroll
        for (int i = NPATH; i < 32; ++i)
            a[i] = 0.0f;

        const bool have2 = (e2 < BATCH);
        if (have2) {            // next even element's burst: ~2 element-times of flight
            z = __ldg(Wl + (size_t)((unsigned)cv2.x + OFFSET) * (NDIM / 4));
            const unsigned bn = (unsigned)cv2.y + OFFSET + 1u;
#pragma unroll
            for (int i = 0; i < NPATH; ++i)
                w[i] = __ldg(Wm1 + (size_t)(bn >> (DEPTH - i)) * (NDIM / 4));
        }

#pragma unroll
        for (int m = 1; m < 32; m <<= 1) {
            const bool hi = (lane & m) != 0;
#pragma unroll
            for (int k = 0; k < 32; k += 2 * m) {
                const float send = hi ? a[k] : a[k + m];
                const float recv = __shfl_xor_sync(0xFFFFFFFFu, send, m);
                a[k] = (hi ? a[k + m] : a[k]) + recv;
            }
        }
        {
            float c = (lane < NPATH) ? (1.0f + __expf(-a[0])) : 1.0f;
#pragma unroll
            for (int o = 16; o > 0; o >>= 1)
                c *= __shfl_xor_sync(0xFFFFFFFFu, c, o);
            if (lane == 0) out[e0] = __fdividef(1.0f, c);
        }

        // ===== ODD phase: element e1 from the smem stage =====
        const bool have1 = (e1 < BATCH);
        if (have1) {
            asm volatile("cp.async.wait_group 0;" ::: "memory");

            const float4 zo = ring[wib][0][lane];
#pragma unroll
            for (int i = 0; i < NPATH; ++i) {
                const float4 q = ring[wib][1 + i][lane];   // LDS.128, conflict-free
                a[i] = q.x * zo.x + q.y * zo.y + q.z * zo.z + q.w * zo.w;
            }
#pragma unroll
            for (int i = NPATH; i < 32; ++i)
                a[i] = 0.0f;

            // refill the stage for e3 (all LDS above already executed)
            if (e3 < BATCH) {
                uint32_t d0 = (uint32_t)__cvta_generic_to_shared(&ring[wib][0][lane]);
                cp16(d0, Wl + (size_t)((unsigned)cv3.x + OFFSET) * (NDIM / 4));
                const unsigned bb = (unsigned)cv3.y + OFFSET + 1u;
#pragma unroll
                for (int i = 0; i < NPATH; ++i) {
                    uint32_t d = (uint32_t)__cvta_generic_to_shared(&ring[wib][1 + i][lane]);
                    cp16(d, Wm1 + (size_t)(bb >> (DEPTH - i)) * (NDIM / 4));
                }
            }
            asm volatile("cp.async.commit_group;" ::: "memory");

#pragma unroll
            for (int m = 1; m < 32; m <<= 1) {
                const bool hi = (lane & m) != 0;
#pragma unroll
                for (int k = 0; k < 32; k += 2 * m) {
                    const float send = hi ? a[k] : a[k + m];
                    const float recv = __shfl_xor_sync(0xFFFFFFFFu, send, m);
                    a[k] = (hi ? a[k + m] : a[k]) + recv;
                }
            }
            float c = (lane < NPATH) ? (1.0f + __expf(-a[0])) : 1.0f;
#pragma unroll
            for (int o = 16; o > 0; o >>= 1)
                c *= __shfl_xor_sync(0xFFFFFFFFu, c, o);
            if (lane == 0) out[e1] = __fdividef(1.0f, c);
        }

        if (!have2) return;
        e0 = e2; e1 = e3; e2 = e4; e3 = e5;
        cv2 = cv4; cv3 = cv5;
    }
}

extern "C" void kernel_launch(void* const* d_in, const int* in_sizes, int n_in,
                              void* d_out, int out_size)
{
    const int*   coll = (const int*)d_in[0];
    const float* W    = (const float*)d_in[1];
    float*       out  = (float*)d_out;

    // 2-warp blocks; exactly one resident wave sized from measured occupancy
    // (accounts for both the register burst and the 22.5KB/block smem ring).
    const int threads = 64;
    int bpsm = 8;
    cudaOccupancyMaxActiveBlocksPerMultiprocessor(
        &bpsm, BinaryTree_65927747993695_kernel, threads, 0);
    if (bpsm < 1) bpsm = 1;
    long long blocks = (long long)bpsm * 148;
    if (blocks > BATCH / 2) blocks = BATCH / 2;
    BinaryTree_65927747993695_kernel<<<(int)blocks, threads>>>(coll, W, out);
}